// round 12
// baseline (speedup 1.0000x reference)
#include <cuda_runtime.h>
#include <cstdint>

#define NVOX (64*64*64)        // 262144 voxels
#define NQ   (NVOX/4)          // 65536 float4 per (b,k) slab
#define BKN  28                // 4 batches * 7 moving parts
#define CHUNKS 32
#define NBLK 896               // 28 bk * 32 chunks; <= 148*7 => all co-resident
#define THREADS 256
#define PH2_STRIDE (NBLK * THREADS)   // 229376 f4 covered in iter 0

// Scratch + barrier state (no allocations allowed)
__device__ float    g_partial[NBLK * 4];
__device__ float    g_coef[BKN * 12];     // [0..8]=M=R-I, [9..11]=d
__device__ unsigned g_count = 0;          // self-resets every launch
__device__ unsigned g_gen   = 0;          // monotonically increasing

// ---------------- helpers ----------------
__device__ __forceinline__ uint32_t smem_u32(const void* p) {
    uint32_t a;
    asm("{ .reg .u64 t; cvta.to.shared.u64 t, %1; cvt.u32.u64 %0, t; }"
        : "=r"(a) : "l"(p));
    return a;
}
__device__ __forceinline__ void cp_async16(uint32_t dst_smem, const void* src) {
    asm volatile("cp.async.cg.shared.global [%0], [%1], 16;"
                 :: "r"(dst_smem), "l"(src) : "memory");
}
#define CP_COMMIT()  asm volatile("cp.async.commit_group;" ::: "memory")
#define CP_WAIT(n)   asm volatile("cp.async.wait_group %0;" :: "n"(n) : "memory")

// ---------------------------------------------------------------------------
// Single fused kernel, single co-resident wave (896 blocks, 7/SM).
//   Phase 1: block (bk,chunk) reduces its 2048-f4 slab chunk via
//            double-buffered cp.async -> (sum m, m*gx, m*gy, m*gz).
//   Barrier: last-arriving block folds 896x4 partials -> 28 coef sets
//            M = R - I, d = p + t - R p; releases via generation bump.
//            Phase-2 mask prefetch is issued BEFORE the spin (overlap).
//   Phase 2: motion[b,c,v] = sum_k mask[b,k,v]*(M_bk[c,:].g_v + d_bk[c]);
//            grid-stride, first 128 blocks take a second tile.
// ---------------------------------------------------------------------------
__global__ void __launch_bounds__(THREADS, 7)
fused_k(const float* __restrict__ mask, const float* __restrict__ grids,
        const float* __restrict__ trans_vec, const float* __restrict__ rot_mat,
        float* __restrict__ out)
{
    extern __shared__ __align__(16) float4 sbuf[];   // 1792 f4 = 28 KB
    __shared__ float ax[64], ay[64], az[64];
    __shared__ float red[8][4];
    __shared__ float fold[BKN][4];
    __shared__ float cf[84];
    __shared__ unsigned sh_gen;
    __shared__ bool is_last;

    const int tid = threadIdx.x;
    const int bid = blockIdx.x;
    const int bk = bid >> 5, chunk = bid & 31;
    const int b = bk / 7, k = bk % 7;

    if (tid == 0) sh_gen = *(volatile unsigned*)&g_gen;   // entry generation
    if (tid < 64) {
        ax[tid] = grids[tid << 12];               // separable meshgrid axes
        ay[tid] = grids[NVOX + (tid << 6)];
        az[tid] = grids[2 * NVOX + tid];
    }

    // -------- Phase 1: double-buffered copy+reduce of 2048 f4 --------
    const float4* m4 = (const float4*)(mask + ((size_t)(b * 8 + k)) * NVOX)
                       + (size_t)chunk * 2048;
    // prologue: sub-chunks 0 and 1 (buffers 0 and 1, 512 f4 each)
#pragma unroll
    for (int c = 0; c < 2; ++c) {
        cp_async16(smem_u32(&sbuf[(c & 1) * 512 + tid]),       &m4[c * 512 + tid]);
        cp_async16(smem_u32(&sbuf[(c & 1) * 512 + 256 + tid]), &m4[c * 512 + 256 + tid]);
        CP_COMMIT();
    }
    __syncthreads();                               // axes + sh_gen visible
    const unsigned gen0 = sh_gen;

    float s0 = 0.f, sx = 0.f, sy = 0.f, sz = 0.f;
#pragma unroll
    for (int c = 0; c < 4; ++c) {
        if (c < 3) CP_WAIT(1); else CP_WAIT(0);
#pragma unroll
        for (int h = 0; h < 2; ++h) {              // slots tid, 256+tid
            const int off  = h * 256 + tid;
            const float4 m = sbuf[(c & 1) * 512 + off];
            const int vloc = (chunk * 2048 + c * 512 + off) << 2;
            const int i  = vloc >> 12;
            const int j  = (vloc >> 6) & 63;
            const int kk = vloc & 63;
            const float ms = (m.x + m.y) + (m.z + m.w);
            s0 += ms;
            sx = fmaf(ax[i], ms, sx);
            sy = fmaf(ay[j], ms, sy);
            sz = fmaf(az[kk],     m.x,
                 fmaf(az[kk + 1], m.y,
                 fmaf(az[kk + 2], m.z,
                 fmaf(az[kk + 3], m.w, sz))));
        }
        if (c + 2 < 4) {                           // issue next sub-chunk
            const int n = c + 2;
            cp_async16(smem_u32(&sbuf[(n & 1) * 512 + tid]),       &m4[n * 512 + tid]);
            cp_async16(smem_u32(&sbuf[(n & 1) * 512 + 256 + tid]), &m4[n * 512 + 256 + tid]);
            CP_COMMIT();
        }
    }

    // warp tree reduce (deterministic)
#pragma unroll
    for (int off = 16; off; off >>= 1) {
        s0 += __shfl_down_sync(0xFFFFFFFFu, s0, off);
        sx += __shfl_down_sync(0xFFFFFFFFu, sx, off);
        sy += __shfl_down_sync(0xFFFFFFFFu, sy, off);
        sz += __shfl_down_sync(0xFFFFFFFFu, sz, off);
    }
    const int w = tid >> 5, l = tid & 31;
    if (l == 0) { red[w][0] = s0; red[w][1] = sx; red[w][2] = sy; red[w][3] = sz; }
    __syncthreads();                               // all phase-1 smem reads done

    // -------- Phase 2 prefetch (independent of coefficients) --------
    const int gidx = bid * THREADS + tid;          // < 229376 always valid
    const int b2   = gidx >> 16;
    const int idx4 = gidx & 65535;
    const float4* mb = (const float4*)mask + ((size_t)b2 * 8) * NQ + idx4;
#pragma unroll
    for (int kq = 0; kq < 7; ++kq)
        cp_async16(smem_u32(&sbuf[kq * 256 + tid]), &mb[(size_t)kq * NQ]);
    CP_COMMIT();
    const float gx0 = __ldg(&grids[(size_t)(idx4 >> 10) << 12]);

    // -------- publish partial, arrive at grid barrier --------
    if (tid == 0) {
        float r0 = 0.f, r1 = 0.f, r2 = 0.f, r3 = 0.f;
#pragma unroll
        for (int i = 0; i < 8; ++i) {
            r0 += red[i][0]; r1 += red[i][1]; r2 += red[i][2]; r3 += red[i][3];
        }
        float* p = g_partial + bid * 4;
        p[0] = r0; p[1] = r1; p[2] = r2; p[3] = r3;
        __threadfence();                           // publish before arrival
        const unsigned arrived = atomicAdd(&g_count, 1u);
        is_last = (arrived == NBLK - 1);
        if (is_last) g_count = 0;                  // reset for next replay
    }
    __syncthreads();

    if (is_last) {
        // fold 896 partials -> coefficients (L2-hot)
        if (tid < BKN * 4) {                       // 112: (bk, comp)
            const int fbk = tid >> 2, comp = tid & 3;
            const float* p = g_partial + (fbk * CHUNKS) * 4 + comp;
            float s = 0.f;
#pragma unroll
            for (int c = 0; c < CHUNKS; ++c)
                s += __ldcg(p + c * 4);
            fold[fbk][comp] = s;
        }
        __syncthreads();
        if (tid < BKN) {
            const float inv = 1.f / fold[tid][0];
            const float pv[3] = { fold[tid][1] * inv, fold[tid][2] * inv, fold[tid][3] * inv };
            const float* R = rot_mat   + tid * 9;
            const float* t = trans_vec + tid * 3;
            float* c = g_coef + tid * 12;
#pragma unroll
            for (int r = 0; r < 3; ++r) {
                const float Rp = R[r * 3] * pv[0] + R[r * 3 + 1] * pv[1] + R[r * 3 + 2] * pv[2];
                c[r * 3 + 0] = R[r * 3 + 0] - (r == 0 ? 1.f : 0.f);
                c[r * 3 + 1] = R[r * 3 + 1] - (r == 1 ? 1.f : 0.f);
                c[r * 3 + 2] = R[r * 3 + 2] - (r == 2 ? 1.f : 0.f);
                c[9 + r]     = pv[r] + t[r] - Rp;
            }
            __threadfence();                       // publish coefs
        }
        __syncthreads();
        if (tid == 0) atomicAdd(&g_gen, 1u);       // release
    } else {
        if (tid == 0) {
            while (*(volatile unsigned*)&g_gen == gen0) { }
            __threadfence();                       // acquire
        }
        __syncthreads();
    }

    // -------- Phase 2: apply --------
    if (tid < 84) cf[tid] = __ldcg(&g_coef[b2 * 84 + tid]);
    __syncthreads();
    CP_WAIT(0);                                    // phase-2 slices landed

    float4* o4 = (float4*)out;
    {
        const int v  = idx4 << 2;
        const int j  = (v >> 6) & 63;
        const int kk = v & 63;
        const float gy = ay[j];
        const float gz[4] = { az[kk], az[kk + 1], az[kk + 2], az[kk + 3] };
        float mot[3][4] = {};
#pragma unroll
        for (int kq = 0; kq < 7; ++kq) {
            const float4 m = sbuf[kq * 256 + tid];
            const float mvv[4] = { m.x, m.y, m.z, m.w };
            const float* c = cf + kq * 12;
#pragma unroll
            for (int cc = 0; cc < 3; ++cc) {
                const float m2   = c[cc * 3 + 2];
                const float base = fmaf(c[cc * 3], gx0, fmaf(c[cc * 3 + 1], gy, c[9 + cc]));
#pragma unroll
                for (int t = 0; t < 4; ++t)
                    mot[cc][t] = fmaf(mvv[t], fmaf(m2, gz[t], base), mot[cc][t]);
            }
        }
#pragma unroll
        for (int cc = 0; cc < 3; ++cc) {
            float4 o = { mot[cc][0], mot[cc][1], mot[cc][2], mot[cc][3] };
            o4[((size_t)b2 * 3 + cc) * NQ + idx4] = o;
        }
    }

    // -------- second tile: first 128 blocks cover remaining 32768 f4 --------
    if (bid < 128) {
        const int g2    = gidx + PH2_STRIDE;       // in [229376, 262144): batch 3
        const int idx4b = g2 & 65535;
        const float4* mb2 = (const float4*)mask + ((size_t)3 * 8) * NQ + idx4b;
        __syncthreads();                           // everyone done with cf
        if (tid < 84) cf[tid] = __ldcg(&g_coef[3 * 84 + tid]);
#pragma unroll
        for (int kq = 0; kq < 7; ++kq)
            cp_async16(smem_u32(&sbuf[kq * 256 + tid]), &mb2[(size_t)kq * NQ]);
        CP_COMMIT();
        const float gxb = __ldg(&grids[(size_t)(idx4b >> 10) << 12]);
        __syncthreads();                           // cf ready
        CP_WAIT(0);

        const int v  = idx4b << 2;
        const int j  = (v >> 6) & 63;
        const int kk = v & 63;
        const float gy = ay[j];
        const float gz[4] = { az[kk], az[kk + 1], az[kk + 2], az[kk + 3] };
        float mot[3][4] = {};
#pragma unroll
        for (int kq = 0; kq < 7; ++kq) {
            const float4 m = sbuf[kq * 256 + tid];
            const float mvv[4] = { m.x, m.y, m.z, m.w };
            const float* c = cf + kq * 12;
#pragma unroll
            for (int cc = 0; cc < 3; ++cc) {
                const float m2   = c[cc * 3 + 2];
                const float base = fmaf(c[cc * 3], gxb, fmaf(c[cc * 3 + 1], gy, c[9 + cc]));
#pragma unroll
                for (int t = 0; t < 4; ++t)
                    mot[cc][t] = fmaf(mvv[t], fmaf(m2, gz[t], base), mot[cc][t]);
            }
        }
#pragma unroll
        for (int cc = 0; cc < 3; ++cc) {
            float4 o = { mot[cc][0], mot[cc][1], mot[cc][2], mot[cc][3] };
            o4[((size_t)3 * 3 + cc) * NQ + idx4b] = o;
        }
    }
}

// ---------------------------------------------------------------------------
extern "C" void kernel_launch(void* const* d_in, const int* in_sizes, int n_in,
                              void* d_out, int out_size)
{
    const float* mask = nullptr;
    const float* tv   = nullptr;
    const float* rm   = nullptr;
    const float* gr   = nullptr;
    for (int i = 0; i < n_in; ++i) {
        switch (in_sizes[i]) {
            case 8388608: mask = (const float*)d_in[i]; break;   // (4,8,64,64,64)
            case 84:      tv   = (const float*)d_in[i]; break;   // (4,7,3)
            case 252:     rm   = (const float*)d_in[i]; break;   // (4,7,3,3)
            case 786432:  gr   = (const float*)d_in[i]; break;   // (3,64,64,64)
        }
    }
    fused_k<<<NBLK, THREADS, 1792 * sizeof(float4)>>>(mask, gr, tv, rm, (float*)d_out);
}

// round 13
// speedup vs baseline: 1.2840x; 1.2840x over previous
#include <cuda_runtime.h>
#include <cstdint>

#define NVOX (64*64*64)        // 262144 voxels
#define NQ   (NVOX/4)          // 65536 float4 per (b,k) slab
#define BKN 28                 // 4 batches * 7 moving parts
#define CHUNKS 32              // partial-reduction chunks per (b,k)
#define NBLOCKS (BKN * CHUNKS) // 896 reduce blocks
#define RED_THREADS 256
#define APPLY_THREADS 256

// Scratch (no allocations allowed)
__device__ float    g_partial[NBLOCKS * 4];
__device__ float    g_coef[BKN * 12];     // [0..8]=M=R-I row-major, [9..11]=d
__device__ unsigned g_count = 0;          // self-resets every launch

// ---------------- helpers ----------------
__device__ __forceinline__ uint32_t smem_u32(const void* p) {
    uint32_t a;
    asm("{ .reg .u64 t; cvta.to.shared.u64 t, %1; cvt.u32.u64 %0, t; }"
        : "=r"(a) : "l"(p));
    return a;
}
__device__ __forceinline__ void cp_async16(uint32_t dst_smem, const void* src) {
    asm volatile("cp.async.cg.shared.global [%0], [%1], 16;"
                 :: "r"(dst_smem), "l"(src) : "memory");
}
__device__ __forceinline__ void pdl_trigger() {
    asm volatile("griddepcontrol.launch_dependents;");
}
__device__ __forceinline__ void pdl_wait() {
    asm volatile("griddepcontrol.wait;" ::: "memory");
}
// ---- packed fp32x2 (Blackwell FFMA2; bit-identical per lane to scalar fmaf) ----
typedef unsigned long long u64;
__device__ __forceinline__ u64 pack2(float lo, float hi) {
    u64 r; asm("mov.b64 %0, {%1, %2};" : "=l"(r) : "f"(lo), "f"(hi)); return r;
}
__device__ __forceinline__ void unpack2(u64 v, float& lo, float& hi) {
    asm("mov.b64 {%0, %1}, %2;" : "=f"(lo), "=f"(hi) : "l"(v));
}
__device__ __forceinline__ u64 fma2(u64 a, u64 b, u64 c) {
    u64 d; asm("fma.rn.f32x2 %0, %1, %2, %3;" : "=l"(d) : "l"(a), "l"(b), "l"(c));
    return d;
}

// ---------------------------------------------------------------------------
// Pass 1 (primary): per-(b,k) weighted sums (sum m, sum m*gx, m*gy, m*gz).
// Unchanged from R10 champion. LAST block folds partials -> coefficients:
// M = R - I, d = p + t - R p.
// ---------------------------------------------------------------------------
__global__ void __launch_bounds__(RED_THREADS, 6)
reduce_k(const float* __restrict__ mask, const float* __restrict__ grids,
         const float* __restrict__ trans_vec, const float* __restrict__ rot_mat)
{
    const int bk    = blockIdx.x >> 5;
    const int chunk = blockIdx.x & 31;
    const int b = bk / 7, k = bk % 7;
    const int tid = threadIdx.x;

    __shared__ __align__(16) float4 buf[2048];      // 32 KB chunk
    __shared__ float ax[64], ay[64], az[64];
    __shared__ float red[8][4];
    __shared__ float fold[BKN][4];
    __shared__ bool  is_last;

    const float4* m4 = (const float4*)(mask + ((size_t)(b * 8 + k)) * NVOX)
                       + (size_t)chunk * 2048;

#pragma unroll
    for (int t = 0; t < 8; ++t)
        cp_async16(smem_u32(&buf[t * RED_THREADS + tid]), &m4[t * RED_THREADS + tid]);
    asm volatile("cp.async.commit_group;" ::: "memory");

    pdl_trigger();                                   // let apply_k start prefetch

    if (tid < 64) {
        ax[tid] = grids[tid << 12];
        ay[tid] = grids[NVOX + (tid << 6)];
        az[tid] = grids[2 * NVOX + tid];
    }
    __syncthreads();

    asm volatile("cp.async.wait_group 0;" ::: "memory");

    const int vbase = chunk * (NVOX / CHUNKS);
    float s0 = 0.f, sx = 0.f, sy = 0.f, sz = 0.f;
#pragma unroll
    for (int t = 0; t < 8; ++t) {
        const int idx4 = t * RED_THREADS + tid;
        const float4 m = buf[idx4];
        const int v  = vbase + (idx4 << 2);
        const int i  = v >> 12;
        const int j  = (v >> 6) & 63;
        const int kk = v & 63;
        const float ms = (m.x + m.y) + (m.z + m.w);
        s0 += ms;
        sx = fmaf(ax[i], ms, sx);
        sy = fmaf(ay[j], ms, sy);
        sz = fmaf(az[kk],     m.x,
             fmaf(az[kk + 1], m.y,
             fmaf(az[kk + 2], m.z,
             fmaf(az[kk + 3], m.w, sz))));
    }

#pragma unroll
    for (int off = 16; off; off >>= 1) {
        s0 += __shfl_down_sync(0xFFFFFFFFu, s0, off);
        sx += __shfl_down_sync(0xFFFFFFFFu, sx, off);
        sy += __shfl_down_sync(0xFFFFFFFFu, sy, off);
        sz += __shfl_down_sync(0xFFFFFFFFu, sz, off);
    }
    const int w = tid >> 5, l = tid & 31;
    if (l == 0) { red[w][0] = s0; red[w][1] = sx; red[w][2] = sy; red[w][3] = sz; }
    __syncthreads();
    if (tid == 0) {
        float r0 = 0.f, r1 = 0.f, r2 = 0.f, r3 = 0.f;
#pragma unroll
        for (int i = 0; i < 8; ++i) {
            r0 += red[i][0]; r1 += red[i][1]; r2 += red[i][2]; r3 += red[i][3];
        }
        float* p = g_partial + blockIdx.x * 4;
        p[0] = r0; p[1] = r1; p[2] = r2; p[3] = r3;
        __threadfence();
        const unsigned arrived = atomicAdd(&g_count, 1u);
        is_last = (arrived == NBLOCKS - 1);
        if (is_last) g_count = 0;
    }
    __syncthreads();
    if (!is_last) return;

    if (tid < BKN * 4) {
        const int fbk  = tid >> 2;
        const int comp = tid & 3;
        const float* p = g_partial + (fbk * CHUNKS) * 4 + comp;
        float s = 0.f;
#pragma unroll
        for (int c = 0; c < CHUNKS; ++c)
            s += __ldcg(p + c * 4);
        fold[fbk][comp] = s;
    }
    __syncthreads();
    if (tid < BKN) {
        const float inv = 1.f / fold[tid][0];
        const float pv[3] = { fold[tid][1] * inv, fold[tid][2] * inv, fold[tid][3] * inv };
        const float* R = rot_mat   + tid * 9;
        const float* t = trans_vec + tid * 3;
        float* c = g_coef + tid * 12;
#pragma unroll
        for (int r = 0; r < 3; ++r) {
            const float Rp = R[r * 3] * pv[0] + R[r * 3 + 1] * pv[1] + R[r * 3 + 2] * pv[2];
            c[r * 3 + 0] = R[r * 3 + 0] - (r == 0 ? 1.f : 0.f);
            c[r * 3 + 1] = R[r * 3 + 1] - (r == 1 ? 1.f : 0.f);
            c[r * 3 + 2] = R[r * 3 + 2] - (r == 2 ? 1.f : 0.f);
            c[9 + r]     = pv[r] + t[r] - Rp;
        }
    }
}

// ---------------------------------------------------------------------------
// Pass 2 (secondary, PDL): prefetch 7 mask slices, wait on primary, build a
// per-block table base2[k][cc][j] (pair-duplicated) + m2x2[k][cc], then the
// inner loop is 2 x LDS.64 + 4 x FFMA2 per (k,cc) — fma-pipe ops per thread
// drop 210 -> 84 with bit-identical results.
// ---------------------------------------------------------------------------
__global__ void __launch_bounds__(APPLY_THREADS, 6)
apply_k(const float* __restrict__ mask, const float* __restrict__ grids,
        float* __restrict__ out)
{
    const int blocksPerB = NQ / APPLY_THREADS;   // 256
    const int b   = blockIdx.x / blocksPerB;
    const int blk = blockIdx.x % blocksPerB;
    const int tid = threadIdx.x;

    __shared__ __align__(16) float4 sbuf[7 * 256];   // 28 KB: 7 mask slices
    __shared__ float az[64];
    __shared__ u64 sb_base[21 * 16];   // [(k*3+cc)*16 + jrel], lanes duplicated
    __shared__ u64 sb_m2[21];          // [(k*3+cc)], lanes duplicated

    const int idx4 = blk * APPLY_THREADS + tid;
    const float4* mb = (const float4*)mask + ((size_t)b * 8) * NQ + idx4;

    // ---- prefetch: independent of primary's results ----
#pragma unroll
    for (int k = 0; k < 7; ++k)
        cp_async16(smem_u32(&sbuf[k * 256 + tid]), &mb[(size_t)k * NQ]);
    asm volatile("cp.async.commit_group;" ::: "memory");

    if (tid < 64) az[tid] = grids[2 * NVOX + tid];
    const float gx = grids[(size_t)(blk >> 2) << 12];   // block-constant x-plane
    const int jbase = (blk & 3) * 16;                   // 16 y-rows per block

    pdl_wait();                                      // primary grid fully done

    // ---- per-block coefficient tables (done once; overlaps cp.async latency) ----
    const float* cg = g_coef + b * 84;
#pragma unroll
    for (int r = 0; r < 2; ++r) {
        const int e = r * APPLY_THREADS + tid;       // 0..335
        if (e < 336) {
            const int jj = e >> 5;                   // wait: 336 = 21*16 -> e/16? 
        }
    }
    // (explicit loop below — kept simple and branch-uniform)
    for (int e = tid; e < 336; e += APPLY_THREADS) {
        const int kc  = e / 16;                      // 0..20 = k*3+cc
        const int jj  = e & 15;
        const int k   = kc / 3, cc = kc % 3;
        const float c0 = __ldcg(&cg[k * 12 + cc * 3 + 0]);
        const float c1 = __ldcg(&cg[k * 12 + cc * 3 + 1]);
        const float c9 = __ldcg(&cg[k * 12 + 9 + cc]);
        const float gy = __ldg(&grids[NVOX + ((size_t)(jbase + jj) << 6)]);
        const float base = fmaf(c0, gx, fmaf(c1, gy, c9));
        sb_base[kc * 16 + jj] = pack2(base, base);
    }
    if (tid < 21) {
        const int k = tid / 3, cc = tid % 3;
        const float m2 = __ldcg(&cg[k * 12 + cc * 3 + 2]);
        sb_m2[tid] = pack2(m2, m2);
    }
    __syncthreads();                                 // tables + az ready

    asm volatile("cp.async.wait_group 0;" ::: "memory");  // own 16B slots ready

    const int v    = idx4 << 2;
    const int jrel = (idx4 >> 4) & 15;
    const int kk   = v & 63;
    const u64 gz01 = pack2(az[kk],     az[kk + 1]);
    const u64 gz23 = pack2(az[kk + 2], az[kk + 3]);

    u64 mot01[3] = {0ull, 0ull, 0ull};
    u64 mot23[3] = {0ull, 0ull, 0ull};
#pragma unroll
    for (int k = 0; k < 7; ++k) {
        const float4 m = sbuf[k * 256 + tid];
        const u64 m01 = pack2(m.x, m.y);
        const u64 m23 = pack2(m.z, m.w);
#pragma unroll
        for (int cc = 0; cc < 3; ++cc) {
            const u64 b2 = sb_base[(k * 3 + cc) * 16 + jrel];
            const u64 q2 = sb_m2[k * 3 + cc];
            const u64 s01 = fma2(q2, gz01, b2);      // = fmaf(m2, gz[t], base)
            const u64 s23 = fma2(q2, gz23, b2);
            mot01[cc] = fma2(m01, s01, mot01[cc]);   // = fmaf(m[t], s, mot)
            mot23[cc] = fma2(m23, s23, mot23[cc]);
        }
    }

    float4* o4 = (float4*)out;
#pragma unroll
    for (int cc = 0; cc < 3; ++cc) {
        float4 o;
        unpack2(mot01[cc], o.x, o.y);
        unpack2(mot23[cc], o.z, o.w);
        o4[((size_t)b * 3 + cc) * NQ + idx4] = o;
    }
}

// ---------------------------------------------------------------------------
extern "C" void kernel_launch(void* const* d_in, const int* in_sizes, int n_in,
                              void* d_out, int out_size)
{
    const float* mask = nullptr;
    const float* tv   = nullptr;
    const float* rm   = nullptr;
    const float* gr   = nullptr;
    for (int i = 0; i < n_in; ++i) {
        switch (in_sizes[i]) {
            case 8388608: mask = (const float*)d_in[i]; break;   // (4,8,64,64,64)
            case 84:      tv   = (const float*)d_in[i]; break;   // (4,7,3)
            case 252:     rm   = (const float*)d_in[i]; break;   // (4,7,3,3)
            case 786432:  gr   = (const float*)d_in[i]; break;   // (3,64,64,64)
        }
    }

    // Primary
    reduce_k<<<NBLOCKS, RED_THREADS>>>(mask, gr, tv, rm);

    // Secondary with Programmatic Dependent Launch
    cudaLaunchConfig_t cfg = {};
    cfg.gridDim  = dim3(4 * (NQ / APPLY_THREADS), 1, 1);
    cfg.blockDim = dim3(APPLY_THREADS, 1, 1);
    cfg.dynamicSmemBytes = 0;
    cfg.stream = 0;
    cudaLaunchAttribute attr[1];
    attr[0].id = cudaLaunchAttributeProgrammaticStreamSerialization;
    attr[0].val.programmaticStreamSerializationAllowed = 1;
    cfg.attrs = attr;
    cfg.numAttrs = 1;
    cudaLaunchKernelEx(&cfg, apply_k, mask, gr, (float*)d_out);
}

// round 14
// speedup vs baseline: 1.4040x; 1.0935x over previous
#include <cuda_runtime.h>
#include <cstdint>

#define NVOX (64*64*64)        // 262144 voxels
#define NQ   (NVOX/4)          // 65536 float4 per (b,k) slab
#define BKN 28                 // 4 batches * 7 moving parts
#define CHUNKS 64              // partial-reduction chunks per (b,k), 16 KB each
#define NBLOCKS (BKN * CHUNKS) // 1792 reduce blocks; 13/SM => single wave (1924)
#define RED_THREADS 128
#define APPLY_THREADS 256

// Scratch (no allocations allowed)
__device__ float    g_partial[NBLOCKS * 4];
__device__ float    g_coef[BKN * 12];     // [0..8]=M=R-I row-major, [9..11]=d
__device__ unsigned g_count = 0;          // self-resets every launch

// ---------------- helpers ----------------
__device__ __forceinline__ uint32_t smem_u32(const void* p) {
    uint32_t a;
    asm("{ .reg .u64 t; cvta.to.shared.u64 t, %1; cvt.u32.u64 %0, t; }"
        : "=r"(a) : "l"(p));
    return a;
}
__device__ __forceinline__ void cp_async16(uint32_t dst_smem, const void* src) {
    asm volatile("cp.async.cg.shared.global [%0], [%1], 16;"
                 :: "r"(dst_smem), "l"(src) : "memory");
}
__device__ __forceinline__ void pdl_trigger() {          // allow dependent grid launch
    asm volatile("griddepcontrol.launch_dependents;");
}
__device__ __forceinline__ void pdl_wait() {             // wait for primary grid done
    asm volatile("griddepcontrol.wait;" ::: "memory");
}

// ---------------------------------------------------------------------------
// Pass 1 (primary): per-(b,k) weighted sums (sum m, sum m*gx, m*gy, m*gz).
// 1792 blocks x 128 threads, 16 KB chunk each, 8 x 16B cp.async per thread.
// Single co-resident wave (13 blocks/SM) -> no wave-quantization tail ahead
// of the coefficient fold. LAST block folds partials -> coefficients:
// M = R - I, d = p + t - R p.
// ---------------------------------------------------------------------------
__global__ void __launch_bounds__(RED_THREADS, 12)
reduce_k(const float* __restrict__ mask, const float* __restrict__ grids,
         const float* __restrict__ trans_vec, const float* __restrict__ rot_mat)
{
    const int bk    = blockIdx.x >> 6;     // / CHUNKS
    const int chunk = blockIdx.x & 63;     // % CHUNKS
    const int b = bk / 7, k = bk % 7;
    const int tid = threadIdx.x;

    __shared__ __align__(16) float4 buf[1024];      // 16 KB chunk
    __shared__ float ax[64], ay[64], az[64];
    __shared__ float red[4][4];
    __shared__ float fold[BKN][4];
    __shared__ bool  is_last;

    const float4* m4 = (const float4*)(mask + ((size_t)(b * 8 + k)) * NVOX)
                       + (size_t)chunk * 1024;

    // ---- 8 async copies per thread, all in flight immediately ----
#pragma unroll
    for (int t = 0; t < 8; ++t)
        cp_async16(smem_u32(&buf[t * RED_THREADS + tid]), &m4[t * RED_THREADS + tid]);
    asm volatile("cp.async.commit_group;" ::: "memory");

    pdl_trigger();                                   // let apply_k start prefetch

    if (tid < 64) {
        ax[tid] = grids[tid << 12];                 // gx[i,0,0]
        ay[tid] = grids[NVOX + (tid << 6)];         // gy[0,j,0]
        az[tid] = grids[2 * NVOX + tid];            // gz[0,0,k]
    }
    __syncthreads();                                 // axes ready

    asm volatile("cp.async.wait_group 0;" ::: "memory");  // own 16B slots ready

    const int vbase = chunk * (NVOX / CHUNKS);       // 4096 voxels per chunk
    float s0 = 0.f, sx = 0.f, sy = 0.f, sz = 0.f;
#pragma unroll
    for (int t = 0; t < 8; ++t) {
        const int idx4 = t * RED_THREADS + tid;
        const float4 m = buf[idx4];                 // conflict-free LDS.128
        const int v  = vbase + (idx4 << 2);
        const int i  = v >> 12;
        const int j  = (v >> 6) & 63;
        const int kk = v & 63;
        const float ms = (m.x + m.y) + (m.z + m.w);
        s0 += ms;
        sx = fmaf(ax[i], ms, sx);
        sy = fmaf(ay[j], ms, sy);
        sz = fmaf(az[kk],     m.x,
             fmaf(az[kk + 1], m.y,
             fmaf(az[kk + 2], m.z,
             fmaf(az[kk + 3], m.w, sz))));
    }

    // warp tree reduce (deterministic)
#pragma unroll
    for (int off = 16; off; off >>= 1) {
        s0 += __shfl_down_sync(0xFFFFFFFFu, s0, off);
        sx += __shfl_down_sync(0xFFFFFFFFu, sx, off);
        sy += __shfl_down_sync(0xFFFFFFFFu, sy, off);
        sz += __shfl_down_sync(0xFFFFFFFFu, sz, off);
    }
    const int w = tid >> 5, l = tid & 31;
    if (l == 0) { red[w][0] = s0; red[w][1] = sx; red[w][2] = sy; red[w][3] = sz; }
    __syncthreads();
    if (tid == 0) {
        float r0 = 0.f, r1 = 0.f, r2 = 0.f, r3 = 0.f;
#pragma unroll
        for (int i = 0; i < 4; ++i) {
            r0 += red[i][0]; r1 += red[i][1]; r2 += red[i][2]; r3 += red[i][3];
        }
        float* p = g_partial + blockIdx.x * 4;
        p[0] = r0; p[1] = r1; p[2] = r2; p[3] = r3;
        __threadfence();                                // publish partial
        const unsigned arrived = atomicAdd(&g_count, 1u);
        is_last = (arrived == NBLOCKS - 1);
        if (is_last) g_count = 0;                       // reset for next replay
    }
    __syncthreads();
    if (!is_last) return;

    // -------- last block: fold partials -> coefficients (L2-hot) --------
    if (tid < BKN * 4) {                 // 112 threads: one (bk, component) each
        const int fbk  = tid >> 2;
        const int comp = tid & 3;
        const float* p = g_partial + (fbk * CHUNKS) * 4 + comp;
        float s = 0.f;
#pragma unroll
        for (int c = 0; c < CHUNKS; ++c)
            s += __ldcg(p + c * 4);
        fold[fbk][comp] = s;
    }
    __syncthreads();
    if (tid < BKN) {
        const float inv = 1.f / fold[tid][0];
        const float pv[3] = { fold[tid][1] * inv, fold[tid][2] * inv, fold[tid][3] * inv };
        const float* R = rot_mat   + tid * 9;
        const float* t = trans_vec + tid * 3;
        float* c = g_coef + tid * 12;
#pragma unroll
        for (int r = 0; r < 3; ++r) {
            const float Rp = R[r * 3] * pv[0] + R[r * 3 + 1] * pv[1] + R[r * 3 + 2] * pv[2];
            c[r * 3 + 0] = R[r * 3 + 0] - (r == 0 ? 1.f : 0.f);
            c[r * 3 + 1] = R[r * 3 + 1] - (r == 1 ? 1.f : 0.f);
            c[r * 3 + 2] = R[r * 3 + 2] - (r == 2 ? 1.f : 0.f);
            c[9 + r]     = pv[r] + t[r] - Rp;
        }
    }
    // g_coef visible to apply_k: griddepcontrol.wait orders on full kernel completion
}

// ---------------------------------------------------------------------------
// Pass 2 (secondary, PDL) — unchanged R10 champion: prefetch 7 x 16B mask
// slices + axes BEFORE the dependency wait; read coefficients after.
// motion[b,c,v] = sum_{k<7} mask[b,k,v] * (M_bk[c,:].g_v + d_bk[c]).
// ---------------------------------------------------------------------------
__global__ void __launch_bounds__(APPLY_THREADS, 6)
apply_k(const float* __restrict__ mask, const float* __restrict__ grids,
        float* __restrict__ out)
{
    const int blocksPerB = NQ / APPLY_THREADS;   // 256
    const int b   = blockIdx.x / blocksPerB;
    const int blk = blockIdx.x % blocksPerB;
    const int tid = threadIdx.x;

    __shared__ __align__(16) float4 sbuf[7 * 256];   // 28 KB: 7 mask slices
    __shared__ float cf[84];
    __shared__ float ay[64], az[64];

    const int idx4 = blk * APPLY_THREADS + tid;
    const float4* mb = (const float4*)mask + ((size_t)b * 8) * NQ + idx4;

    // ---- prefetch: independent of primary's results ----
#pragma unroll
    for (int k = 0; k < 7; ++k)
        cp_async16(smem_u32(&sbuf[k * 256 + tid]), &mb[(size_t)k * NQ]);
    asm volatile("cp.async.commit_group;" ::: "memory");

    if (tid < 64) {
        ay[tid] = grids[NVOX + (tid << 6)];
        az[tid] = grids[2 * NVOX + tid];
    }
    const float gx = grids[(size_t)(blk >> 2) << 12];   // block-constant x-plane

    pdl_wait();                                      // primary grid fully done

    if (tid < 84) cf[tid] = g_coef[b * 84 + tid];    // coefficients now final
    __syncthreads();                                 // cf + axes ready

    asm volatile("cp.async.wait_group 0;" ::: "memory");  // own 16B slots ready

    const int v  = idx4 << 2;
    const int j  = (v >> 6) & 63;
    const int kk = v & 63;
    const float gy = ay[j];
    const float gz[4] = { az[kk], az[kk + 1], az[kk + 2], az[kk + 3] };

    float mot[3][4] = {};
#pragma unroll
    for (int k = 0; k < 7; ++k) {
        const float4 m = sbuf[k * 256 + tid];
        const float mvv[4] = { m.x, m.y, m.z, m.w };
        const float* c = cf + k * 12;
#pragma unroll
        for (int cc = 0; cc < 3; ++cc) {
            const float m2   = c[cc * 3 + 2];
            const float base = fmaf(c[cc * 3], gx, fmaf(c[cc * 3 + 1], gy, c[9 + cc]));
#pragma unroll
            for (int t = 0; t < 4; ++t)
                mot[cc][t] = fmaf(mvv[t], fmaf(m2, gz[t], base), mot[cc][t]);
        }
    }

    float4* o4 = (float4*)out;
#pragma unroll
    for (int cc = 0; cc < 3; ++cc) {
        float4 o = { mot[cc][0], mot[cc][1], mot[cc][2], mot[cc][3] };
        o4[((size_t)b * 3 + cc) * NQ + idx4] = o;
    }
}

// ---------------------------------------------------------------------------
extern "C" void kernel_launch(void* const* d_in, const int* in_sizes, int n_in,
                              void* d_out, int out_size)
{
    const float* mask = nullptr;
    const float* tv   = nullptr;
    const float* rm   = nullptr;
    const float* gr   = nullptr;
    for (int i = 0; i < n_in; ++i) {
        switch (in_sizes[i]) {
            case 8388608: mask = (const float*)d_in[i]; break;   // (4,8,64,64,64)
            case 84:      tv   = (const float*)d_in[i]; break;   // (4,7,3)
            case 252:     rm   = (const float*)d_in[i]; break;   // (4,7,3,3)
            case 786432:  gr   = (const float*)d_in[i]; break;   // (3,64,64,64)
        }
    }

    // Primary
    reduce_k<<<NBLOCKS, RED_THREADS>>>(mask, gr, tv, rm);

    // Secondary with Programmatic Dependent Launch: begins its prefetch while
    // reduce_k drains; griddepcontrol.wait guards the coefficient read.
    cudaLaunchConfig_t cfg = {};
    cfg.gridDim  = dim3(4 * (NQ / APPLY_THREADS), 1, 1);
    cfg.blockDim = dim3(APPLY_THREADS, 1, 1);
    cfg.dynamicSmemBytes = 0;
    cfg.stream = 0;                                  // legacy default stream (captured)
    cudaLaunchAttribute attr[1];
    attr[0].id = cudaLaunchAttributeProgrammaticStreamSerialization;
    attr[0].val.programmaticStreamSerializationAllowed = 1;
    cfg.attrs = attr;
    cfg.numAttrs = 1;
    cudaLaunchKernelEx(&cfg, apply_k, mask, gr, (float*)d_out);
}